// round 16
// baseline (speedup 1.0000x reference)
#include <cuda_runtime.h>
#include <cstdint>
#include <cmath>

// freqs_j = fl32(pi_f * exp_IEEE(fl32(j*ln2_f)))  — table now computed HOST-side
// (double exp; f32-rounding has 2^9 ulps of slack vs device double exp, proven
// equivalent by R11 pass at 3e-8) and passed by value -> no init kernel in the
// graph, no global table loads (param constant bank instead).
//
// ang_j = fl32(x * freqs_j) = fl32(x * s_j) * 2^j,  s_j = freqs_j * 2^-j (exact)
// Anchor at exponent E-1 (M2 = 2M, 25 bits): every yc = fl(x*s_j) is an exact
// integer multiple M2 + k of the anchor ulp. Phase u_j = U0' + khat_j*hi
// (khat via magic-FMA, bias pre-folded). h_j = top32(u_j << j) = exact 32-bit
// turn fraction; theta = (int)h * 2pi/2^32 in [-pi, pi); RRO+MUFU sincos.

#define W0 0x28BE60DB9391054AULL   // 1/(2*pi) fraction bits 1..64
#define W1 0x7F09D5F47D4D3770ULL   // bits 65..128

struct Scales { float2 s[16]; };   // (s_{2p}, s_{2p+1}), 128 bytes by value

// One level: exact ulp offset via magic-FMA, phase via U0' + khat*hi, MUFU sincos.
static __device__ __forceinline__ float2 level_cs(
    float xv, float s, float y0, float invulp,
    unsigned long long U0p, unsigned long long hi, int j)
{
    float yc = __fmul_rn(xv, s);
    float d  = __fsub_rn(yc, y0);                      // exact (Sterbenz)
    // khat = 0x4B400000 + k, exact for |k| < 2^22 (here |k| <= ~84)
    unsigned khat = __float_as_uint(__fmaf_rn(d, invulp, 12582912.0f));
    unsigned long long u = U0p + (unsigned long long)khat * hi;
    unsigned h = __funnelshift_rc((unsigned)u, (unsigned)(u >> 32),
                                  (unsigned)(32 - j));
    float th = (float)(int)h * 1.46291807926715968e-9f;  // 2pi/2^32 -> [-pi, pi)
    float sv, cv;
    __sincosf(th, &sv, &cv);                           // RRO + MUFU.SIN + MUFU.COS
    return make_float2(cv, sv);
}

__global__ void __launch_bounds__(256)
encoder_kernel(const float* __restrict__ x, float4* __restrict__ out, int n,
               Scales sc) {
    unsigned gtid = blockIdx.x * blockDim.x + threadIdx.x;   // < n*4 = 2^24
    unsigned e = gtid >> 2;          // element
    unsigned p = gtid & 3;           // owns float4 slots p, p+4, p+8, p+12
    if (e >= (unsigned)n) return;

    float xv = __ldg(&x[e]);

    // ---- anchor at exponent E-1: y0 = M2 * 2^(E-151), M2 = 2*M (25 bits) ----
    float y0 = __fmul_rn(xv, 3.14159265358979323846f);
    unsigned iy = __float_as_uint(y0);
    int E = (int)(iy >> 23);
    unsigned M2 = (((iy & 0x7FFFFFu) | 0x800000u) << 1);
    int t = E - 87;                          // window shift, t in [1, 41] normally
    unsigned long long hi = 0ULL, lo = 0ULL;
    if (t >= 1) {                            // else x == 0 -> all phases 0
        hi = W0 >> (64 - t);
        lo = (W0 << t) | (W1 >> (64 - t));
    }
    // U0 = M2*hi + floor(M2*lo / 2^64); fold out the magic-FMA bias
    unsigned long long a = (unsigned long long)M2 * (unsigned)(lo >> 32);
    unsigned long long b = (unsigned long long)M2 * (unsigned)lo;
    unsigned long long U0 = (unsigned long long)M2 * hi + ((a + (b >> 32)) >> 32);
    unsigned long long U0p = U0 - 0x4B400000ULL * hi;   // u = U0p + khat*hi

    // invulp = 2^(151-E): exact d -> ulp-count scale (clamped for tiny E)
    int fld = 278 - E; if (fld > 254) fld = 254; if (fld < 1) fld = 1;
    float invulp = __uint_as_float((unsigned)fld << 23);

    // ---- 8 levels in 4 slot-pairs: compute all, then store back-to-back ----
    float4 r[4];
    #pragma unroll
    for (int ss = 0; ss < 4; ss++) {
        int slot = (int)p + 4 * ss;          // j-pair index
        float2 sv = sc.s[slot];              // param constant bank (LDC)
        int j = 2 * slot;
        float2 c0 = level_cs(xv, sv.x, y0, invulp, U0p, hi, j);
        float2 c1 = level_cs(xv, sv.y, y0, invulp, U0p, hi, j + 1);
        r[ss] = make_float4(c0.x, c0.y, c1.x, c1.y);
    }
    unsigned idx = 4u * gtid - 3u * p;       // = 16*e + p
    #pragma unroll
    for (int ss = 0; ss < 4; ss++)
        __stcs(&out[idx + 4u * ss], r[ss]);
}

extern "C" void kernel_launch(void* const* d_in, const int* in_sizes, int n_in,
                              void* d_out, int out_size) {
    const float* x = (const float*)d_in[0];
    int n = in_sizes[0];

    // Host-side reconstruction of the reference freq table (every call;
    // deterministic, allocation-free). Matches device double-exp path (R11).
    Scales sc;
    const float LN2_F = 0.693147180559945309417f;   // fl32 -> 0x3F317218
    const float PI_F  = 3.14159265358979323846f;    // fl32 -> 0x40490FDB
    for (int j = 0; j < 32; j++) {
        float aa = (float)j * LN2_F;                // fl32(j * ln2_f)
        double ev = std::exp((double)aa);           // IEEE double exp
        float fr = PI_F * (float)ev;                // reference freq bits
        ((float*)sc.s)[j] = ldexpf(fr, -j);         // exact scale ~pi*(1 +- 2.5e-6)
    }

    long long total = (long long)n * 4;      // one thread per 4 output float4s
    int threads = 256;
    int blocks = (int)((total + threads - 1) / threads);
    encoder_kernel<<<blocks, threads>>>(x, (float4*)d_out, n, sc);
}

// round 17
// speedup vs baseline: 3.1887x; 3.1887x over previous
#include <cuda_runtime.h>
#include <cstdint>
#include <cmath>

// freqs_j = fl32(pi_f * exp_IEEE(fl32(j*ln2_f))) — table computed host-side each
// call (bit-identical to device double-exp table: R15 vs R16 rel_err match) and
// passed via __grid_constant__ param -> real const-memory address, dynamic
// indexing compiles to LDC (NO local-memory spill, which caused R16's 3.2x).
//
// ang_j = fl32(x * freqs_j) = fl32(x * s_j) * 2^j,  s_j = freqs_j * 2^-j (exact)
// Anchor at exponent E-1 (M2 = 2M, 25 bits): every yc = fl(x*s_j) is an exact
// integer multiple M2 + k of the anchor ulp. Phase u_j = U0' + khat_j*hi
// (khat via magic-FMA, bias pre-folded). h_j = top32(u_j << j) = exact 32-bit
// turn fraction; theta = (int)h * 2pi/2^32 in [-pi, pi); RRO+MUFU sincos.

#define W0 0x28BE60DB9391054AULL   // 1/(2*pi) fraction bits 1..64
#define W1 0x7F09D5F47D4D3770ULL   // bits 65..128

struct Scales { float2 s[16]; };   // (s_{2p}, s_{2p+1}), 128 bytes

// One level: exact ulp offset via magic-FMA, phase via U0' + khat*hi, MUFU sincos.
static __device__ __forceinline__ float2 level_cs(
    float xv, float s, float y0, float invulp,
    unsigned long long U0p, unsigned long long hi, int j)
{
    float yc = __fmul_rn(xv, s);
    float d  = __fsub_rn(yc, y0);                      // exact (Sterbenz)
    // khat = 0x4B400000 + k, exact for |k| < 2^22 (here |k| <= ~84)
    unsigned khat = __float_as_uint(__fmaf_rn(d, invulp, 12582912.0f));
    unsigned long long u = U0p + (unsigned long long)khat * hi;
    unsigned h = __funnelshift_rc((unsigned)u, (unsigned)(u >> 32),
                                  (unsigned)(32 - j));
    float th = (float)(int)h * 1.46291807926715968e-9f;  // 2pi/2^32 -> [-pi, pi)
    float sv, cv;
    __sincosf(th, &sv, &cv);                           // RRO + MUFU.SIN + MUFU.COS
    return make_float2(cv, sv);
}

__global__ void __launch_bounds__(256)
encoder_kernel(const float* __restrict__ x, float4* __restrict__ out, int n,
               const __grid_constant__ Scales sc) {
    unsigned gtid = blockIdx.x * blockDim.x + threadIdx.x;   // < n*4 = 2^24
    unsigned e = gtid >> 2;          // element
    unsigned p = gtid & 3;           // owns float4 slots p, p+4, p+8, p+12
    if (e >= (unsigned)n) return;

    float xv = __ldg(&x[e]);

    // ---- anchor at exponent E-1: y0 = M2 * 2^(E-151), M2 = 2*M (25 bits) ----
    float y0 = __fmul_rn(xv, 3.14159265358979323846f);
    unsigned iy = __float_as_uint(y0);
    int E = (int)(iy >> 23);
    unsigned M2 = (((iy & 0x7FFFFFu) | 0x800000u) << 1);
    int t = E - 87;                          // window shift, t in [1, 41] normally
    unsigned long long hi = 0ULL, lo = 0ULL;
    if (t >= 1) {                            // else x == 0 -> all phases 0
        hi = W0 >> (64 - t);
        lo = (W0 << t) | (W1 >> (64 - t));
    }
    // U0 = M2*hi + floor(M2*lo / 2^64); fold out the magic-FMA bias
    unsigned long long a = (unsigned long long)M2 * (unsigned)(lo >> 32);
    unsigned long long b = (unsigned long long)M2 * (unsigned)lo;
    unsigned long long U0 = (unsigned long long)M2 * hi + ((a + (b >> 32)) >> 32);
    unsigned long long U0p = U0 - 0x4B400000ULL * hi;   // u = U0p + khat*hi

    // invulp = 2^(151-E): exact d -> ulp-count scale (clamped for tiny E)
    int fld = 278 - E; if (fld > 254) fld = 254; if (fld < 1) fld = 1;
    float invulp = __uint_as_float((unsigned)fld << 23);

    // ---- 8 levels in 4 slot-pairs; store each float4 as soon as ready ----
    unsigned idx = 4u * gtid - 3u * p;       // = 16*e + p
    #pragma unroll
    for (int ss = 0; ss < 4; ss++) {
        int slot = (int)p + 4 * ss;          // j-pair index
        float2 sv = sc.s[slot];              // LDC from const bank (no spill)
        int j = 2 * slot;
        float2 c0 = level_cs(xv, sv.x, y0, invulp, U0p, hi, j);
        float2 c1 = level_cs(xv, sv.y, y0, invulp, U0p, hi, j + 1);
        __stcs(&out[idx + 4u * ss], make_float4(c0.x, c0.y, c1.x, c1.y));
    }
}

extern "C" void kernel_launch(void* const* d_in, const int* in_sizes, int n_in,
                              void* d_out, int out_size) {
    const float* x = (const float*)d_in[0];
    int n = in_sizes[0];

    // Host-side reconstruction of the reference freq table (every call;
    // deterministic, allocation-free; bit-identical to device double-exp path).
    Scales sc;
    const float LN2_F = 0.693147180559945309417f;   // fl32 -> 0x3F317218
    const float PI_F  = 3.14159265358979323846f;    // fl32 -> 0x40490FDB
    for (int j = 0; j < 32; j++) {
        float aa = (float)j * LN2_F;                // fl32(j * ln2_f)
        double ev = std::exp((double)aa);           // IEEE double exp
        float fr = PI_F * (float)ev;                // reference freq bits
        ((float*)sc.s)[j] = ldexpf(fr, -j);         // exact scale ~pi*(1 +- 2.5e-6)
    }

    long long total = (long long)n * 4;      // one thread per 4 output float4s
    int threads = 256;
    int blocks = (int)((total + threads - 1) / threads);
    encoder_kernel<<<blocks, threads>>>(x, (float4*)d_out, n, sc);
}